// round 2
// baseline (speedup 1.0000x reference)
#include <cuda_runtime.h>

#define F 256
#define F4 (F / 4)                  // 64 float4 per row
#define TOTAL_ROWS (32 * 4096)      // B*T = 131072
#define STATS_BLOCKS 1024
#define ROWS_PER_BLOCK (TOTAL_ROWS / STATS_BLOCKS)   // 128
#define EPS 1e-5f

// Scratch (no cudaMalloc allowed)
__device__ float        g_sum[F];
__device__ float        g_sumsq[F];
__device__ unsigned int g_count;
__device__ unsigned int g_ticket;
__device__ float        g_scale[F];
__device__ float        g_bias[F];

// ---------------------------------------------------------------------------
// Kernel 0: zero accumulators (graph replays must be idempotent)
// ---------------------------------------------------------------------------
__global__ void init_kernel() {
    int t = threadIdx.x;
    g_sum[t]   = 0.0f;
    g_sumsq[t] = 0.0f;
    if (t == 0) { g_count = 0u; g_ticket = 0u; }
}

// ---------------------------------------------------------------------------
// Kernel 1: per-feature sum / sumsq over masked rows + fused finalize.
//   - thread = one float4 of one row-slot: f4 = tid&63, sub = tid>>6
//   - 4 rows in flight per block, LDG.128, unroll 4  -> high MLP
//   - mask branch uniform across the 64 threads of a row-slot
//   - smem reduce across the 4 row-slots, then 1 atomic per feature per block
//   - last block (ticket) computes scale/bias  -> no separate finalize launch
// ---------------------------------------------------------------------------
__global__ void __launch_bounds__(256) stats_kernel(const float* __restrict__ x,
                                                    const int*   __restrict__ mask,
                                                    const float* __restrict__ gamma,
                                                    const float* __restrict__ beta) {
    const int tid = threadIdx.x;
    const int f4  = tid & 63;       // float4 column within row
    const int sub = tid >> 6;       // row slot 0..3
    const int row0 = blockIdx.x * ROWS_PER_BLOCK;

    const float4* __restrict__ x4 = (const float4*)x;

    float4 acc  = make_float4(0.f, 0.f, 0.f, 0.f);
    float4 acc2 = make_float4(0.f, 0.f, 0.f, 0.f);
    int cnt = 0;

#pragma unroll 1
    for (int g = 0; g < ROWS_PER_BLOCK / 4; g += 4) {
#pragma unroll
        for (int u = 0; u < 4; u++) {
            const int r = row0 + (g + u) * 4 + sub;
            if (mask[r] > 0) {
                float4 v = x4[(size_t)r * F4 + f4];
                acc.x += v.x; acc.y += v.y; acc.z += v.z; acc.w += v.w;
                acc2.x += v.x * v.x; acc2.y += v.y * v.y;
                acc2.z += v.z * v.z; acc2.w += v.w * v.w;
                cnt++;
            }
        }
    }

    // ---- intra-block reduction across the 4 row-slots ----
    __shared__ float4 s_sum[256];
    __shared__ float4 s_sq[256];
    __shared__ int    s_cnt[4];
    __shared__ bool   s_last;
    s_sum[tid] = acc;
    s_sq[tid]  = acc2;
    if (f4 == 0) s_cnt[sub] = cnt;
    __syncthreads();

    if (sub == 0) {
#pragma unroll
        for (int k = 1; k < 4; k++) {
            float4 a = s_sum[tid + 64 * k];
            float4 b = s_sq[tid + 64 * k];
            acc.x += a.x; acc.y += a.y; acc.z += a.z; acc.w += a.w;
            acc2.x += b.x; acc2.y += b.y; acc2.z += b.z; acc2.w += b.w;
        }
        const int fb = f4 * 4;
        atomicAdd(&g_sum[fb + 0], acc.x);
        atomicAdd(&g_sum[fb + 1], acc.y);
        atomicAdd(&g_sum[fb + 2], acc.z);
        atomicAdd(&g_sum[fb + 3], acc.w);
        atomicAdd(&g_sumsq[fb + 0], acc2.x);
        atomicAdd(&g_sumsq[fb + 1], acc2.y);
        atomicAdd(&g_sumsq[fb + 2], acc2.z);
        atomicAdd(&g_sumsq[fb + 3], acc2.w);
        if (tid == 0) {
            atomicAdd(&g_count,
                      (unsigned)(s_cnt[0] + s_cnt[1] + s_cnt[2] + s_cnt[3]));
        }
    }

    // ---- last block finalizes scale/bias ----
    __threadfence();
    __syncthreads();
    if (tid == 0) {
        unsigned t = atomicAdd(&g_ticket, 1u);
        s_last = (t == (unsigned)(gridDim.x - 1));
    }
    __syncthreads();
    if (s_last) {
        // all prior blocks' atomics are globally visible (fence + ticket)
        float cntf = (float)g_count;
        float mean = g_sum[tid] / cntf;
        float var  = g_sumsq[tid] / cntf - mean * mean;
        float s    = rsqrtf(var + EPS) * gamma[tid];
        g_scale[tid] = s;
        g_bias[tid]  = beta[tid] - mean * s;
    }
}

// ---------------------------------------------------------------------------
// Kernel 2: apply. float4-vectorized; mask branch warp-uniform.
// (Already within ~4% of mixed read+write HBM floor — unchanged.)
// ---------------------------------------------------------------------------
__global__ void __launch_bounds__(256) apply_kernel(const float* __restrict__ x,
                                                    const int*   __restrict__ mask,
                                                    float*       __restrict__ out) {
    const size_t i = (size_t)blockIdx.x * blockDim.x + threadIdx.x;  // float4 index
    const float4* __restrict__ x4 = (const float4*)x;
    float4* __restrict__ out4 = (float4*)out;

    const int row = (int)(i >> 6);       // 64 float4 per row
    const int f4  = (int)(i & 63);

    float4 v = x4[i];
    if (mask[row] > 0) {
        const float4* s4 = (const float4*)g_scale;
        const float4* b4 = (const float4*)g_bias;
        float4 s = s4[f4];
        float4 b = b4[f4];
        v.x = fmaf(v.x, s.x, b.x);
        v.y = fmaf(v.y, s.y, b.y);
        v.z = fmaf(v.z, s.z, b.z);
        v.w = fmaf(v.w, s.w, b.w);
    }
    out4[i] = v;
}

// ---------------------------------------------------------------------------
extern "C" void kernel_launch(void* const* d_in, const int* in_sizes, int n_in,
                              void* d_out, int out_size) {
    const float* x     = (const float*)d_in[0];
    const int*   mask  = (const int*)d_in[1];
    const float* gamma = (const float*)d_in[2];
    const float* beta  = (const float*)d_in[3];
    float*       out   = (float*)d_out;

    init_kernel<<<1, 256>>>();
    stats_kernel<<<STATS_BLOCKS, 256>>>(x, mask, gamma, beta);
    // 32*4096*256 / 4 = 8,388,608 float4 -> 32768 blocks of 256
    apply_kernel<<<32768, 256>>>(x, mask, out);
}

// round 3
// speedup vs baseline: 1.0003x; 1.0003x over previous
#include <cuda_runtime.h>

#define F 256
#define F4 (F / 4)                  // 64 float4 per row
#define TOTAL_ROWS (32 * 4096)      // B*T = 131072
#define STATS_BLOCKS 1024
#define ROWS_PER_BLOCK (TOTAL_ROWS / STATS_BLOCKS)   // 128
#define EPS 1e-5f

// Scratch (no cudaMalloc allowed)
__device__ float        g_sum[F];
__device__ float        g_sumsq[F];
__device__ unsigned int g_count;
__device__ float        g_scale[F];
__device__ float        g_bias[F];
__device__ float        g_zero4[4] = {0.f, 0.f, 0.f, 0.f};  // decoy target for unmasked rows

// ---------------------------------------------------------------------------
// Kernel 0: zero accumulators (graph replays must be idempotent)
// ---------------------------------------------------------------------------
__global__ void init_kernel() {
    int t = threadIdx.x;
    g_sum[t]   = 0.0f;
    g_sumsq[t] = 0.0f;
    if (t == 0) g_count = 0u;
}

// ---------------------------------------------------------------------------
// Kernel 1: per-feature sum / sumsq over masked rows.
// Branchless masking: the load address is SELected between the real row and
// a shared zero word. No control flow -> ptxas front-batches all 8 LDG.128
// per unroll group (high MLP); unmasked rows cost a broadcast L1 hit and add
// exact zeros. DRAM read volume stays ~= masked rows only (~64 MB).
//   thread = one float4 column of one row-slot: f4 = tid&63, sub = tid>>6
// ---------------------------------------------------------------------------
__global__ void __launch_bounds__(256) stats_kernel(const float* __restrict__ x,
                                                    const int*   __restrict__ mask) {
    const int tid  = threadIdx.x;
    const int f4   = tid & 63;      // float4 column within row
    const int sub  = tid >> 6;      // row slot 0..3
    const int row0 = blockIdx.x * ROWS_PER_BLOCK;

    const float4* __restrict__ x4 = (const float4*)x;
    const float4* zp = (const float4*)g_zero4;

    float4 acc  = make_float4(0.f, 0.f, 0.f, 0.f);
    float4 acc2 = make_float4(0.f, 0.f, 0.f, 0.f);
    int cnt = 0;

#pragma unroll 1
    for (int i = 0; i < ROWS_PER_BLOCK / 4; i += 8) {
        const float4* p[8];
        int mv[8];
#pragma unroll
        for (int u = 0; u < 8; u++) {
            const int r = row0 + (i + u) * 4 + sub;
            mv[u] = mask[r];
            p[u] = (mv[u] > 0) ? (x4 + (size_t)r * F4 + f4) : zp;
        }
#pragma unroll
        for (int u = 0; u < 8; u++) {
            float4 v = *p[u];
            acc.x  += v.x;       acc.y  += v.y;
            acc.z  += v.z;       acc.w  += v.w;
            acc2.x += v.x * v.x; acc2.y += v.y * v.y;
            acc2.z += v.z * v.z; acc2.w += v.w * v.w;
            cnt += (mv[u] > 0);
        }
    }

    // ---- intra-block reduction across the 4 row-slots ----
    __shared__ float4 s_sum[256];
    __shared__ float4 s_sq[256];
    __shared__ int    s_cnt[4];
    s_sum[tid] = acc;
    s_sq[tid]  = acc2;
    if (f4 == 0) s_cnt[sub] = cnt;
    __syncthreads();

    if (sub == 0) {
#pragma unroll
        for (int k = 1; k < 4; k++) {
            float4 a = s_sum[tid + 64 * k];
            float4 b = s_sq[tid + 64 * k];
            acc.x += a.x; acc.y += a.y; acc.z += a.z; acc.w += a.w;
            acc2.x += b.x; acc2.y += b.y; acc2.z += b.z; acc2.w += b.w;
        }
        const int fb = f4 * 4;
        atomicAdd(&g_sum[fb + 0], acc.x);
        atomicAdd(&g_sum[fb + 1], acc.y);
        atomicAdd(&g_sum[fb + 2], acc.z);
        atomicAdd(&g_sum[fb + 3], acc.w);
        atomicAdd(&g_sumsq[fb + 0], acc2.x);
        atomicAdd(&g_sumsq[fb + 1], acc2.y);
        atomicAdd(&g_sumsq[fb + 2], acc2.z);
        atomicAdd(&g_sumsq[fb + 3], acc2.w);
        if (tid == 0) {
            atomicAdd(&g_count,
                      (unsigned)(s_cnt[0] + s_cnt[1] + s_cnt[2] + s_cnt[3]));
        }
    }
}

// ---------------------------------------------------------------------------
// Kernel 2: finalize — fold mean/var/gamma/beta into per-feature affine.
// ---------------------------------------------------------------------------
__global__ void finalize_kernel(const float* __restrict__ gamma,
                                const float* __restrict__ beta) {
    int f = threadIdx.x;
    float cnt  = (float)g_count;
    float mean = g_sum[f] / cnt;
    float var  = g_sumsq[f] / cnt - mean * mean;
    float s    = rsqrtf(var + EPS) * gamma[f];
    g_scale[f] = s;
    g_bias[f]  = beta[f] - mean * s;
}

// ---------------------------------------------------------------------------
// Kernel 3: apply. float4-vectorized; mask branch warp-uniform.
// (~94% of mixed read+write HBM floor — unchanged.)
// ---------------------------------------------------------------------------
__global__ void __launch_bounds__(256) apply_kernel(const float* __restrict__ x,
                                                    const int*   __restrict__ mask,
                                                    float*       __restrict__ out) {
    const size_t i = (size_t)blockIdx.x * blockDim.x + threadIdx.x;  // float4 index
    const float4* __restrict__ x4 = (const float4*)x;
    float4* __restrict__ out4 = (float4*)out;

    const int row = (int)(i >> 6);       // 64 float4 per row
    const int f4  = (int)(i & 63);

    float4 v = x4[i];
    if (mask[row] > 0) {
        const float4* s4 = (const float4*)g_scale;
        const float4* b4 = (const float4*)g_bias;
        float4 s = s4[f4];
        float4 b = b4[f4];
        v.x = fmaf(v.x, s.x, b.x);
        v.y = fmaf(v.y, s.y, b.y);
        v.z = fmaf(v.z, s.z, b.z);
        v.w = fmaf(v.w, s.w, b.w);
    }
    out4[i] = v;
}

// ---------------------------------------------------------------------------
extern "C" void kernel_launch(void* const* d_in, const int* in_sizes, int n_in,
                              void* d_out, int out_size) {
    const float* x     = (const float*)d_in[0];
    const int*   mask  = (const int*)d_in[1];
    const float* gamma = (const float*)d_in[2];
    const float* beta  = (const float*)d_in[3];
    float*       out   = (float*)d_out;

    init_kernel<<<1, 256>>>();
    stats_kernel<<<STATS_BLOCKS, 256>>>(x, mask);
    finalize_kernel<<<1, 256>>>(gamma, beta);
    // 32*4096*256 / 4 = 8,388,608 float4 -> 32768 blocks of 256
    apply_kernel<<<32768, 256>>>(x, mask, out);
}